// round 4
// baseline (speedup 1.0000x reference)
#include <cuda_runtime.h>
#include <math_constants.h>

#define NGRAPHS 2048
#define NUMK    128
#define NE      1024
#define HD      32
#define ROWLEN  (NUMK + NE + 2)

// Built once per launch by gcn_prep (edge template + weights identical across graphs).
__device__ int g_csr[NE];                       // packed: src | dst<<8 | eid<<16
__device__ int g_ptr[NUMK + 1];
__device__ float g_t[HD];                       // relu thresholds t_k = -b1k/W1k
__device__ __align__(16) float g_A[33 * HD];    // h = s1*A[iv] + C[iv]
__device__ __align__(16) float g_C[33 * HD];

__global__ void gcn_prep(const int* __restrict__ ew,
                         const float* __restrict__ W1,
                         const float* __restrict__ b1,
                         const float* __restrict__ W2) {
    __shared__ unsigned char src_sh[NE], dst_sh[NE];
    __shared__ int cnt[NUMK];
    __shared__ int base_sh[NUMK + 1];
    __shared__ int odd_nonzero;
    __shared__ float t_sh[HD], tsort[HD], srep[33];
    __shared__ unsigned int mask_sh[33];
    int t = threadIdx.x;  // 128 threads

    // ---------- part 1: dst-sorted CSR (int32 vs int64 layout guard) ----------
    if (t == 0) odd_nonzero = 0;
    __syncthreads();
    for (int i = t * 2 + 1; i < 2 * NE; i += 256)
        if (ew[i] != 0) odd_nonzero = 1;
    __syncthreads();
    const bool is64 = (odd_nonzero == 0);
    for (int e = t; e < NE; e += 128) {
        int s, d;
        if (is64) { s = ew[2 * e]; d = ew[2 * (NE + e)]; }
        else      { s = ew[e];     d = ew[NE + e]; }
        src_sh[e] = (unsigned char)(s & 127);
        dst_sh[e] = (unsigned char)(d & 127);
    }
    cnt[t] = 0;
    __syncthreads();
    for (int e = t; e < NE; e += 128) atomicAdd(&cnt[dst_sh[e]], 1);
    __syncthreads();
    if (t == 0) {
        int acc = 0;
        for (int n = 0; n < NUMK; n++) { base_sh[n] = acc; acc += cnt[n]; }
        base_sh[NUMK] = acc;
    }
    __syncthreads();
    g_ptr[t] = base_sh[t];
    if (t == 0) g_ptr[NUMK] = base_sh[NUMK];
    cnt[t] = 0;
    __syncthreads();
    for (int e = t; e < NE; e += 128) {
        int d = dst_sh[e];
        int pos = base_sh[d] + atomicAdd(&cnt[d], 1);
        if (pos < NE)
            g_csr[pos] = (int)src_sh[e] | (d << 8) | (e << 16);
    }

    // ---------- part 2: piecewise-linear tables for h = relu(s1*W1+b1) @ W2 ----
    if (t < HD) {
        float w1 = W1[t], bv = b1[t];
        float tk = (w1 == 0.f) ? CUDART_INF_F : (-bv / w1);
        t_sh[t] = tk;
        g_t[t]  = tk;
    }
    __syncthreads();
    if (t < HD) {
        float tk = t_sh[t];
        int r = 0;
        for (int m = 0; m < HD; m++) {
            float tm = t_sh[m];
            r += (tm < tk) || (tm == tk && m < t);
        }
        tsort[r] = tk;
    }
    __syncthreads();
    if (t < 33) {
        float s;
        if (t == 0)       s = tsort[0] - fabsf(tsort[0]) - 1.f;
        else if (t == 32) s = tsort[31] + fabsf(tsort[31]) + 1.f;
        else              s = 0.5f * (tsort[t - 1] + tsort[t]);
        srep[t] = s;
    }
    __syncthreads();
    if (t < 33) {
        float s = srep[t];
        unsigned m = 0;
        for (int k = 0; k < HD; k++) {
            float w1 = W1[k], tk = t_sh[k];
            bool act = (w1 > 0.f) ? (s > tk)
                     : (w1 < 0.f) ? (s < tk)
                                  : (b1[k] > 0.f);
            if (act) m |= 1u << k;
        }
        mask_sh[t] = m;
    }
    __syncthreads();
    {
        int j = t & 31, grp = t >> 5;                  // 4 groups of 9 intervals
        int iv0 = grp * 9, iv1 = min(33, iv0 + 9);
        float accA[9], accC[9];
        unsigned lm[9];
        #pragma unroll
        for (int i = 0; i < 9; i++) { accA[i] = 0.f; accC[i] = 0.f; lm[i] = 0u; }
        for (int i = iv0; i < iv1; i++) lm[i - iv0] = mask_sh[i];
        for (int k = 0; k < HD; k++) {
            float w2 = W2[k * HD + j];
            float a = W1[k] * w2, c = b1[k] * w2;
            #pragma unroll
            for (int i = 0; i < 9; i++)
                if ((lm[i] >> k) & 1u) { accA[i] += a; accC[i] += c; }
        }
        for (int i = iv0; i < iv1; i++) {
            g_A[i * HD + j] = accA[i - iv0];
            g_C[i * HD + j] = accC[i - iv0];
        }
    }
}

// One CTA per graph, 256 threads. norm = dinv_s*w*dinv_d is never materialized:
// node vectors are pre-scaled by dinv and the aggregation post-scales by dinv_dst.
__global__ __launch_bounds__(256) void gcn_main(
    const float* __restrict__ Hx,
    const float* __restrict__ b2,
    const float* __restrict__ W3,
    const float* __restrict__ b3,
    float* __restrict__ out)
{
    __shared__ float  p_s[NUMK];                  // p, then p' = dinv*p
    __shared__ float  w_s[NE];
    __shared__ int    csr_s[NE];
    __shared__ int    ptr_s[NUMK + 1];
    __shared__ float  deg_s[NUMK];                // deg, then dinv
    __shared__ float  s1_s[NUMK];
    __shared__ float2 sc_s[NUMK];                 // (s1_final, dinv)
    __shared__ float  h3_s[NUMK];
    __shared__ float2 ns_s[NE];                   // (w, src*8)
    __shared__ __align__(16) float h_s[NUMK * HD];   // h' = dinv * h
    __shared__ __align__(16) float A_s[33 * HD], C_s[33 * HD];
    __shared__ __align__(16) float b2_s[HD], W3_s[HD];

    const int g    = blockIdx.x;
    const int tid  = threadIdx.x;
    const int lane = tid & 31;
    const int warp = tid >> 5;
    const float* row = Hx + (long long)g * ROWLEN;   // 8B-aligned for all g

    // ---- stage ----
    {
        const float2* rp = (const float2*)row;
        if (tid < 64) {
            float2 v = rp[tid];
            p_s[2 * tid] = v.x; p_s[2 * tid + 1] = v.y;
        }
        for (int i = tid; i < NE / 2; i += 256) {
            float2 v = rp[64 + i];
            w_s[2 * i] = v.x; w_s[2 * i + 1] = v.y;
        }
        for (int i = tid; i < NE / 4; i += 256)
            ((int4*)csr_s)[i] = ((const int4*)g_csr)[i];
        if (tid <= NUMK) ptr_s[tid] = g_ptr[tid];
        if (tid < HD) { b2_s[tid] = b2[tid]; W3_s[tid] = W3[tid]; }
        for (int i = tid; i < (33 * HD) / 4; i += 256) {
            ((float4*)A_s)[i] = ((const float4*)g_A)[i];
            ((float4*)C_s)[i] = ((const float4*)g_C)[i];
        }
        if (tid < NUMK) { deg_s[tid] = 1.0f; s1_s[tid] = 0.f; }
    }
    const float tl = __ldg(&g_t[lane]);
    __syncthreads();

    // ---- pass A: edge-parallel; stash (w, src*8); accumulate degree ----
    for (int s = tid; s < NE; s += 256) {
        int pk = csr_s[s];
        float w = w_s[(pk >> 16) & 1023];
        ns_s[s] = make_float2(w, __int_as_float((pk & 255) * 8));
        atomicAdd(&deg_s[(pk >> 8) & 255], w);
    }
    __syncthreads();

    // ---- dinv; pre-scale p ----
    if (tid < NUMK) {
        float deg = deg_s[tid];
        float di = (deg > 0.f) ? rsqrtf(deg) : 0.f;
        deg_s[tid] = di;
        p_s[tid] *= di;                            // p'
    }
    __syncthreads();

    // ---- pass B: edge-parallel layer-1 scalar aggregation ----
    for (int s = tid; s < NE; s += 256) {
        float2 f = ns_s[s];
        int dst = (csr_s[s] >> 8) & 255;
        atomicAdd(&s1_s[dst], f.x * p_s[__float_as_int(f.y) >> 3]);
    }
    __syncthreads();

    if (tid < NUMK) {
        float di = deg_s[tid];
        sc_s[tid] = make_float2(di * (s1_s[tid] + p_s[tid]), di);
    }
    __syncthreads();

    // ---- pass C: h' = dinv*(s1*A[iv] + C[iv]) via ballot interval lookup ----
    #pragma unroll
    for (int i = 0; i < 16; i++) {
        const int n = (warp << 4) + i;
        float2 sc = sc_s[n];
        unsigned bl = __ballot_sync(0xffffffffu, tl < sc.x);
        int iv = __popc(bl);
        h_s[n * HD + lane] =
            sc.y * fmaf(sc.x, A_s[iv * HD + lane], C_s[iv * HD + lane]);
    }
    __syncthreads();

    // ---- pass D: layer-2 aggregation (float4, 4 nodes/warp) + relu + dot W3 ----
    {
        const int li  = lane & 7;
        const int sub = lane >> 3;
        const float4 b24 = *(const float4*)&b2_s[li * 4];
        const float4 w34 = *(const float4*)&W3_s[li * 4];
        const float4* hb = (const float4*)h_s;
        #pragma unroll
        for (int ps = 0; ps < 4; ps++) {
            const int n = (warp << 4) + ps * 4 + sub;
            const float di = sc_s[n].y;
            float4 acc = hb[n * 8 + li];             // self term (h')
            const int beg = ptr_s[n], end = ptr_s[n + 1];
            for (int s = beg; s < end; s++) {
                float2 f = ns_s[s];
                float4 hv = hb[__float_as_int(f.y) + li];
                acc.x = fmaf(f.x, hv.x, acc.x);
                acc.y = fmaf(f.x, hv.y, acc.y);
                acc.z = fmaf(f.x, hv.z, acc.z);
                acc.w = fmaf(f.x, hv.w, acc.w);
            }
            float v = fmaxf(fmaf(di, acc.x, b24.x), 0.f) * w34.x
                    + fmaxf(fmaf(di, acc.y, b24.y), 0.f) * w34.y
                    + fmaxf(fmaf(di, acc.z, b24.z), 0.f) * w34.z
                    + fmaxf(fmaf(di, acc.w, b24.w), 0.f) * w34.w;
            v += __shfl_xor_sync(0xffffffffu, v, 4);
            v += __shfl_xor_sync(0xffffffffu, v, 2);
            v += __shfl_xor_sync(0xffffffffu, v, 1);
            if (li == 0) h3_s[n] = di * v;           // pre-scaled t'
        }
    }
    __syncthreads();

    // ---- pass E: layer-3 scalar aggregation -> output ----
    if (tid < NUMK) {
        float acc = h3_s[tid];                       // self term (t')
        const int beg = ptr_s[tid], end = ptr_s[tid + 1];
        for (int s = beg; s < end; s++) {
            float2 f = ns_s[s];
            acc = fmaf(f.x, h3_s[__float_as_int(f.y) >> 3], acc);
        }
        out[(long long)g * NUMK + tid] = fmaf(deg_s[tid], acc, __ldg(&b3[0]));
    }
}

extern "C" void kernel_launch(void* const* d_in, const int* in_sizes, int n_in,
                              void* d_out, int out_size) {
    const float* Hx = (const float*)d_in[0];
    const int*   ei = (const int*)d_in[1];
    const float* W1 = (const float*)d_in[2];
    const float* b1 = (const float*)d_in[3];
    const float* W2 = (const float*)d_in[4];
    const float* b2 = (const float*)d_in[5];
    const float* W3 = (const float*)d_in[6];
    const float* b3 = (const float*)d_in[7];
    float* out = (float*)d_out;

    gcn_prep<<<1, 128>>>(ei, W1, b1, W2);
    gcn_main<<<NGRAPHS, 256>>>(Hx, b2, W3, b3, out);
}

// round 5
// speedup vs baseline: 1.1110x; 1.1110x over previous
#include <cuda_runtime.h>
#include <math_constants.h>

#define NGRAPHS 2048
#define NUMK    128
#define NE      1024
#define HD      32
#define ROWLEN  (NUMK + NE + 2)

// Built once per launch (edge template + weights identical across graphs).
__device__ int g_csr[NE];                       // packed: src | dst<<8 | eid<<16
__device__ int g_ptr[NUMK + 1];
__device__ float g_t[HD];                       // relu thresholds t_k = -b1k/W1k
__device__ __align__(16) float g_A[33 * HD];    // h = s1*A[iv] + C[iv]
__device__ __align__(16) float g_C[33 * HD];

// ---------------- prep 1: dst-sorted CSR (single CTA, cheap) ----------------
__global__ void gcn_prep_csr(const int* __restrict__ ew) {
    __shared__ unsigned char src_sh[NE], dst_sh[NE];
    __shared__ int cnt[NUMK];
    __shared__ int base_sh[NUMK + 1];
    __shared__ int odd_nonzero;
    int t = threadIdx.x;  // 128 threads
    if (t == 0) odd_nonzero = 0;
    __syncthreads();
    for (int i = t * 2 + 1; i < 2 * NE; i += 256)    // int32 vs int64 layout guard
        if (ew[i] != 0) odd_nonzero = 1;
    __syncthreads();
    const bool is64 = (odd_nonzero == 0);
    for (int e = t; e < NE; e += 128) {
        int s, d;
        if (is64) { s = ew[2 * e]; d = ew[2 * (NE + e)]; }
        else      { s = ew[e];     d = ew[NE + e]; }
        src_sh[e] = (unsigned char)(s & 127);
        dst_sh[e] = (unsigned char)(d & 127);
    }
    cnt[t] = 0;
    __syncthreads();
    for (int e = t; e < NE; e += 128) atomicAdd(&cnt[dst_sh[e]], 1);
    __syncthreads();
    // warp-parallel prefix sum over 128 counts (4 warp scans + offsets)
    {
        int lane = t & 31, w = t >> 5;
        int v = cnt[t];
        int sc = v;
        #pragma unroll
        for (int o = 1; o < 32; o <<= 1) {
            int u = __shfl_up_sync(0xffffffffu, sc, o);
            if (lane >= o) sc += u;
        }
        __shared__ int wsum[4];
        if (lane == 31) wsum[w] = sc;
        __syncthreads();
        int off = 0;
        for (int i = 0; i < w; i++) off += wsum[i];
        base_sh[t] = off + sc - v;                 // exclusive scan
        if (t == 127) base_sh[NUMK] = off + sc;
        __syncthreads();
    }
    g_ptr[t] = base_sh[t];
    if (t == 0) g_ptr[NUMK] = base_sh[NUMK];
    cnt[t] = 0;
    __syncthreads();
    for (int e = t; e < NE; e += 128) {
        int d = dst_sh[e];
        int pos = base_sh[d] + atomicAdd(&cnt[d], 1);
        if (pos < NE)
            g_csr[pos] = (int)src_sh[e] | (d << 8) | (e << 16);
    }
}

// --------- prep 2: piecewise-linear tables, one block per interval ----------
__global__ void gcn_prep_tab(const float* __restrict__ W1,
                             const float* __restrict__ b1,
                             const float* __restrict__ W2) {
    __shared__ float t_sh[HD], w1_sh[HD], b1_sh[HD], tsort[HD];
    __shared__ unsigned int mask_sh;
    const int j  = threadIdx.x;                   // 32 threads
    const int iv = blockIdx.x;                    // 0..32
    float w1 = W1[j], bv = b1[j];
    w1_sh[j] = w1; b1_sh[j] = bv;
    float tk = (w1 == 0.f) ? CUDART_INF_F : (-bv / w1);
    t_sh[j] = tk;
    if (iv == 0) g_t[j] = tk;
    __syncwarp();
    int r = 0;
    #pragma unroll
    for (int m = 0; m < HD; m++) {
        float tm = t_sh[m];
        r += (tm < tk) || (tm == tk && m < j);
    }
    tsort[r] = tk;
    __syncwarp();
    if (j == 0) {
        float s;
        if (iv == 0)       s = tsort[0] - fabsf(tsort[0]) - 1.f;
        else if (iv == 32) s = tsort[31] + fabsf(tsort[31]) + 1.f;
        else               s = 0.5f * (tsort[iv - 1] + tsort[iv]);
        unsigned m = 0;
        for (int k = 0; k < HD; k++) {
            float w = w1_sh[k], tt = t_sh[k];
            bool act = (w > 0.f) ? (s > tt)
                     : (w < 0.f) ? (s < tt)
                                 : (b1_sh[k] > 0.f);
            if (act) m |= 1u << k;
        }
        mask_sh = m;
    }
    __syncwarp();
    const unsigned m = mask_sh;
    float accA = 0.f, accC = 0.f;
    #pragma unroll
    for (int k = 0; k < HD; k++) {
        if ((m >> k) & 1u) {
            float w2 = __ldg(&W2[k * HD + j]);    // coalesced across j
            accA = fmaf(w1_sh[k], w2, accA);
            accC = fmaf(b1_sh[k], w2, accC);
        }
    }
    g_A[iv * HD + j] = accA;
    g_C[iv * HD + j] = accC;
}

// One CTA per graph, 256 threads. norm never materialized: vectors pre-scaled
// by dinv, aggregation post-scaled by dinv_dst.
__global__ __launch_bounds__(256) void gcn_main(
    const float* __restrict__ Hx,
    const float* __restrict__ b2,
    const float* __restrict__ W3,
    const float* __restrict__ b3,
    float* __restrict__ out)
{
    __shared__ float  p_s[NUMK];                  // p, then p' = dinv*p
    __shared__ float  w_s[NE];
    __shared__ int    csr_s[NE];
    __shared__ int    ptr_s[NUMK + 1];
    __shared__ float  deg_s[NUMK];                // deg, then dinv
    __shared__ float  s1_s[NUMK];
    __shared__ float2 sc_s[NUMK];                 // (s1_final, dinv)
    __shared__ float  h3_s[NUMK];
    __shared__ float2 ns_s[NE];                   // (w, src*8)
    __shared__ __align__(16) float h_s[NUMK * HD];
    __shared__ __align__(16) float A_s[33 * HD], C_s[33 * HD];
    __shared__ __align__(16) float b2_s[HD], W3_s[HD];

    const int g    = blockIdx.x;
    const int tid  = threadIdx.x;
    const int lane = tid & 31;
    const int warp = tid >> 5;
    const float* row = Hx + (long long)g * ROWLEN;

    // ---- stage ----
    {
        const float2* rp = (const float2*)row;
        if (tid < 64) {
            float2 v = rp[tid];
            p_s[2 * tid] = v.x; p_s[2 * tid + 1] = v.y;
        }
        for (int i = tid; i < NE / 2; i += 256) {
            float2 v = rp[64 + i];
            w_s[2 * i] = v.x; w_s[2 * i + 1] = v.y;
        }
        for (int i = tid; i < NE / 4; i += 256)
            ((int4*)csr_s)[i] = ((const int4*)g_csr)[i];
        if (tid <= NUMK) ptr_s[tid] = g_ptr[tid];
        if (tid < HD) { b2_s[tid] = b2[tid]; W3_s[tid] = W3[tid]; }
        for (int i = tid; i < (33 * HD) / 4; i += 256) {
            ((float4*)A_s)[i] = ((const float4*)g_A)[i];
            ((float4*)C_s)[i] = ((const float4*)g_C)[i];
        }
        if (tid < NUMK) { deg_s[tid] = 1.0f; s1_s[tid] = 0.f; }
    }
    const float tl = __ldg(&g_t[lane]);
    __syncthreads();

    // ---- pass A: edge-parallel; stash (w, src*8); accumulate degree ----
    for (int s = tid; s < NE; s += 256) {
        int pk = csr_s[s];
        float w = w_s[(pk >> 16) & 1023];
        ns_s[s] = make_float2(w, __int_as_float((pk & 255) * 8));
        atomicAdd(&deg_s[(pk >> 8) & 255], w);
    }
    __syncthreads();

    if (tid < NUMK) {
        float deg = deg_s[tid];
        float di = (deg > 0.f) ? rsqrtf(deg) : 0.f;
        deg_s[tid] = di;
        p_s[tid] *= di;                            // p'
    }
    __syncthreads();

    // ---- pass B: edge-parallel layer-1 scalar aggregation ----
    for (int s = tid; s < NE; s += 256) {
        float2 f = ns_s[s];
        int dst = (csr_s[s] >> 8) & 255;
        atomicAdd(&s1_s[dst], f.x * p_s[__float_as_int(f.y) >> 3]);
    }
    __syncthreads();

    if (tid < NUMK) {
        float di = deg_s[tid];
        sc_s[tid] = make_float2(di * (s1_s[tid] + p_s[tid]), di);
    }
    __syncthreads();

    // ---- pass C: h' = dinv*(s1*A[iv] + C[iv]) via ballot interval lookup ----
    #pragma unroll
    for (int i = 0; i < 16; i++) {
        const int n = (warp << 4) + i;
        float2 sc = sc_s[n];
        unsigned bl = __ballot_sync(0xffffffffu, tl < sc.x);
        int iv = __popc(bl);
        h_s[n * HD + lane] =
            sc.y * fmaf(sc.x, A_s[iv * HD + lane], C_s[iv * HD + lane]);
    }
    __syncthreads();

    // ---- pass D: layer-2 aggregation (float4, 4 nodes/warp, x2 unroll) ----
    {
        const int li  = lane & 7;
        const int sub = lane >> 3;
        const float4 b24 = *(const float4*)&b2_s[li * 4];
        const float4 w34 = *(const float4*)&W3_s[li * 4];
        const float4* hb = (const float4*)h_s;
        #pragma unroll
        for (int ps = 0; ps < 4; ps++) {
            const int n = (warp << 4) + ps * 4 + sub;
            const float di = sc_s[n].y;
            float4 acc  = hb[n * 8 + li];            // self term (h')
            float4 acc2 = make_float4(0.f, 0.f, 0.f, 0.f);
            const int beg = ptr_s[n], end = ptr_s[n + 1];
            int s = beg;
            for (; s + 1 < end; s += 2) {
                float2 f0 = ns_s[s];
                float2 f1 = ns_s[s + 1];
                float4 h0 = hb[__float_as_int(f0.y) + li];
                float4 h1 = hb[__float_as_int(f1.y) + li];
                acc.x  = fmaf(f0.x, h0.x, acc.x);
                acc.y  = fmaf(f0.x, h0.y, acc.y);
                acc.z  = fmaf(f0.x, h0.z, acc.z);
                acc.w  = fmaf(f0.x, h0.w, acc.w);
                acc2.x = fmaf(f1.x, h1.x, acc2.x);
                acc2.y = fmaf(f1.x, h1.y, acc2.y);
                acc2.z = fmaf(f1.x, h1.z, acc2.z);
                acc2.w = fmaf(f1.x, h1.w, acc2.w);
            }
            if (s < end) {
                float2 f0 = ns_s[s];
                float4 h0 = hb[__float_as_int(f0.y) + li];
                acc.x = fmaf(f0.x, h0.x, acc.x);
                acc.y = fmaf(f0.x, h0.y, acc.y);
                acc.z = fmaf(f0.x, h0.z, acc.z);
                acc.w = fmaf(f0.x, h0.w, acc.w);
            }
            acc.x += acc2.x; acc.y += acc2.y; acc.z += acc2.z; acc.w += acc2.w;
            float v = fmaxf(fmaf(di, acc.x, b24.x), 0.f) * w34.x
                    + fmaxf(fmaf(di, acc.y, b24.y), 0.f) * w34.y
                    + fmaxf(fmaf(di, acc.z, b24.z), 0.f) * w34.z
                    + fmaxf(fmaf(di, acc.w, b24.w), 0.f) * w34.w;
            v += __shfl_xor_sync(0xffffffffu, v, 4);
            v += __shfl_xor_sync(0xffffffffu, v, 2);
            v += __shfl_xor_sync(0xffffffffu, v, 1);
            if (li == 0) h3_s[n] = di * v;           // pre-scaled t'
        }
    }
    __syncthreads();

    // ---- pass E: layer-3 scalar aggregation (x2 unroll) -> output ----
    if (tid < NUMK) {
        float acc = h3_s[tid], acc2 = 0.f;
        const int beg = ptr_s[tid], end = ptr_s[tid + 1];
        int s = beg;
        for (; s + 1 < end; s += 2) {
            float2 f0 = ns_s[s];
            float2 f1 = ns_s[s + 1];
            acc  = fmaf(f0.x, h3_s[__float_as_int(f0.y) >> 3], acc);
            acc2 = fmaf(f1.x, h3_s[__float_as_int(f1.y) >> 3], acc2);
        }
        if (s < end) {
            float2 f0 = ns_s[s];
            acc = fmaf(f0.x, h3_s[__float_as_int(f0.y) >> 3], acc);
        }
        out[(long long)g * NUMK + tid] =
            fmaf(deg_s[tid], acc + acc2, __ldg(&b3[0]));
    }
}

extern "C" void kernel_launch(void* const* d_in, const int* in_sizes, int n_in,
                              void* d_out, int out_size) {
    const float* Hx = (const float*)d_in[0];
    const int*   ei = (const int*)d_in[1];
    const float* W1 = (const float*)d_in[2];
    const float* b1 = (const float*)d_in[3];
    const float* W2 = (const float*)d_in[4];
    const float* b2 = (const float*)d_in[5];
    const float* W3 = (const float*)d_in[6];
    const float* b3 = (const float*)d_in[7];
    float* out = (float*)d_out;

    gcn_prep_csr<<<1, 128>>>(ei);
    gcn_prep_tab<<<33, 32>>>(W1, b1, W2);
    gcn_main<<<NGRAPHS, 256>>>(Hx, b2, W3, b3, out);
}

// round 6
// speedup vs baseline: 1.3637x; 1.2275x over previous
#include <cuda_runtime.h>
#include <math_constants.h>

#define NGRAPHS 2048
#define NUMK    128
#define NE      1024
#define HD      32
#define ROWLEN  (NUMK + NE + 2)

// Built once per launch (edge template + weights identical across graphs).
__device__ int g_csr[NE];                       // packed: src | dst<<8 | eid<<16
__device__ int g_ptr[NUMK + 1];
__device__ float g_t[HD];                       // relu thresholds t_k = -b1k/W1k
__device__ __align__(16) float g_A[33 * HD];    // h = s1*A[iv] + C[iv]
__device__ __align__(16) float g_C[33 * HD];

// ---- single prep launch: block 0 = CSR build; blocks 1..33 = table rows ----
__global__ __launch_bounds__(256) void gcn_prep(const int* __restrict__ ew,
                                                const float* __restrict__ W1,
                                                const float* __restrict__ b1,
                                                const float* __restrict__ W2) {
    if (blockIdx.x == 0) {
        // ---------- dst-sorted CSR (256 threads) ----------
        __shared__ unsigned char src_sh[NE], dst_sh[NE];
        __shared__ int cnt[NUMK];
        __shared__ int base_sh[NUMK + 1];
        __shared__ int wsum[4];
        __shared__ int odd_nonzero;
        const int t = threadIdx.x;
        if (t == 0) odd_nonzero = 0;
        if (t < NUMK) cnt[t] = 0;
        __syncthreads();
        // int32 vs int64 layout guard: odd words all-zero => little-endian int64
        int nz = 0;
        for (int i = t * 2 + 1; i < 2 * NE; i += 512) nz |= ew[i];
        if (nz) odd_nonzero = 1;
        __syncthreads();
        const bool is64 = (odd_nonzero == 0);
        for (int e = t; e < NE; e += 256) {
            int s, d;
            if (is64) { s = ew[2 * e]; d = ew[2 * (NE + e)]; }
            else      { s = ew[e];     d = ew[NE + e]; }
            src_sh[e] = (unsigned char)(s & 127);
            dst_sh[e] = (unsigned char)(d & 127);
        }
        __syncthreads();
        for (int e = t; e < NE; e += 256) atomicAdd(&cnt[dst_sh[e]], 1);
        __syncthreads();
        // exclusive prefix over 128 counts (4 warp scans + offsets)
        if (t < NUMK) {
            int lane = t & 31, w = t >> 5;
            int v = cnt[t];
            int sc = v;
            #pragma unroll
            for (int o = 1; o < 32; o <<= 1) {
                int u = __shfl_up_sync(0xffffffffu, sc, o);
                if (lane >= o) sc += u;
            }
            if (lane == 31) wsum[w] = sc;
            __syncwarp();
        }
        __syncthreads();
        if (t < NUMK) {
            int w = t >> 5;
            int off = 0;
            for (int i = 0; i < w; i++) off += wsum[i];
            int sc;
            {   // recompute inclusive scan value cheaply from cnt
                int lane = t & 31;
                int v = cnt[t];
                sc = v;
                #pragma unroll
                for (int o = 1; o < 32; o <<= 1) {
                    int u = __shfl_up_sync(0xffffffffu, sc, o);
                    if (lane >= o) sc += u;
                }
                base_sh[t] = off + sc - v;
                if (t == 127) base_sh[NUMK] = off + sc;
            }
            g_ptr[t] = base_sh[t];
            if (t == 127) g_ptr[NUMK] = base_sh[NUMK];
            cnt[t] = 0;
        }
        __syncthreads();
        for (int e = t; e < NE; e += 256) {
            int d = dst_sh[e];
            int pos = base_sh[d] + atomicAdd(&cnt[d], 1);
            if (pos < NE)
                g_csr[pos] = (int)src_sh[e] | (d << 8) | (e << 16);
        }
    } else {
        // ---------- piecewise-linear table row (warp 0 only) ----------
        const int j = threadIdx.x;
        if (j >= 32) return;
        __shared__ float t_sh[HD], w1_sh[HD], b1_sh[HD], tsort[HD];
        __shared__ unsigned int mask_sh;
        const int iv = blockIdx.x - 1;            // 0..32
        float w1 = W1[j], bv = b1[j];
        w1_sh[j] = w1; b1_sh[j] = bv;
        float tk = (w1 == 0.f) ? CUDART_INF_F : (-bv / w1);
        t_sh[j] = tk;
        if (iv == 0) g_t[j] = tk;
        __syncwarp();
        int r = 0;
        #pragma unroll
        for (int m = 0; m < HD; m++) {
            float tm = t_sh[m];
            r += (tm < tk) || (tm == tk && m < j);
        }
        tsort[r] = tk;
        __syncwarp();
        if (j == 0) {
            float s;
            if (iv == 0)       s = tsort[0] - fabsf(tsort[0]) - 1.f;
            else if (iv == 32) s = tsort[31] + fabsf(tsort[31]) + 1.f;
            else               s = 0.5f * (tsort[iv - 1] + tsort[iv]);
            unsigned m = 0;
            for (int k = 0; k < HD; k++) {
                float w = w1_sh[k], tt = t_sh[k];
                bool act = (w > 0.f) ? (s > tt)
                         : (w < 0.f) ? (s < tt)
                                     : (b1_sh[k] > 0.f);
                if (act) m |= 1u << k;
            }
            mask_sh = m;
        }
        __syncwarp();
        const unsigned m = mask_sh;
        float accA = 0.f, accC = 0.f;
        #pragma unroll
        for (int k = 0; k < HD; k++) {
            if ((m >> k) & 1u) {
                float w2 = __ldg(&W2[k * HD + j]);
                accA = fmaf(w1_sh[k], w2, accA);
                accC = fmaf(b1_sh[k], w2, accC);
            }
        }
        g_A[iv * HD + j] = accA;
        g_C[iv * HD + j] = accC;
    }
}

// One CTA per graph, 256 threads. norm never materialized: vectors pre-scaled
// by dinv, aggregation post-scaled by dinv_dst.
__global__ __launch_bounds__(256, 6) void gcn_main(
    const float* __restrict__ Hx,
    const float* __restrict__ b2,
    const float* __restrict__ W3,
    const float* __restrict__ b3,
    float* __restrict__ out)
{
    __shared__ float  p_s[NUMK];                  // p, then p' = dinv*p
    __shared__ float  w_s[NE];
    __shared__ int    ptr_s[NUMK + 1];
    __shared__ float  deg_s[NUMK];                // deg, then dinv
    __shared__ float2 sc_s[NUMK];                 // (s1_final, dinv)
    __shared__ float  h3_s[NUMK];
    __shared__ float2 ns_s[NE];                   // (w, src*8)
    __shared__ __align__(16) float h_s[NUMK * HD];
    __shared__ __align__(16) float b2_s[HD], W3_s[HD];

    const int g    = blockIdx.x;
    const int tid  = threadIdx.x;
    const int lane = tid & 31;
    const int warp = tid >> 5;
    const float* row = Hx + (long long)g * ROWLEN;

    // ---- stage ----
    {
        const float2* rp = (const float2*)row;
        if (tid < 64) {
            float2 v = rp[tid];
            p_s[2 * tid] = v.x; p_s[2 * tid + 1] = v.y;
        }
        for (int i = tid; i < NE / 2; i += 256) {
            float2 v = rp[64 + i];
            w_s[2 * i] = v.x; w_s[2 * i + 1] = v.y;
        }
        if (tid <= NUMK) ptr_s[tid] = g_ptr[tid];
        if (tid < HD) { b2_s[tid] = b2[tid]; W3_s[tid] = W3[tid]; }
        if (tid < NUMK) deg_s[tid] = 1.0f;
    }
    const float tl = __ldg(&g_t[lane]);
    __syncthreads();

    // ---- pass A: edge-parallel; stash (w, src*8); accumulate degree ----
    for (int s = tid; s < NE; s += 256) {
        int pk = __ldg(&g_csr[s]);
        float w = w_s[(pk >> 16) & 1023];
        ns_s[s] = make_float2(w, __int_as_float((pk & 255) * 8));
        atomicAdd(&deg_s[(pk >> 8) & 255], w);
    }
    __syncthreads();

    int begN = 0, endN = 0;
    if (tid < NUMK) {
        begN = ptr_s[tid]; endN = ptr_s[tid + 1];
        float deg = deg_s[tid];
        float di = (deg > 0.f) ? rsqrtf(deg) : 0.f;
        deg_s[tid] = di;
        p_s[tid] *= di;                            // p'
    }
    __syncthreads();

    // ---- pass B: node-parallel layer-1 scalar aggregation ----
    if (tid < NUMK) {
        float acc = p_s[tid], acc2 = 0.f;          // self term
        int s = begN;
        for (; s + 1 < endN; s += 2) {
            float2 f0 = ns_s[s];
            float2 f1 = ns_s[s + 1];
            acc  = fmaf(f0.x, p_s[__float_as_int(f0.y) >> 3], acc);
            acc2 = fmaf(f1.x, p_s[__float_as_int(f1.y) >> 3], acc2);
        }
        if (s < endN) {
            float2 f0 = ns_s[s];
            acc = fmaf(f0.x, p_s[__float_as_int(f0.y) >> 3], acc);
        }
        float di = deg_s[tid];
        sc_s[tid] = make_float2(di * (acc + acc2), di);
    }
    __syncthreads();

    // ---- pass C: h' = dinv*(s1*A[iv] + C[iv]) via ballot interval lookup ----
    #pragma unroll
    for (int i = 0; i < 16; i++) {
        const int n = (warp << 4) + i;
        float2 sc = sc_s[n];
        unsigned bl = __ballot_sync(0xffffffffu, tl < sc.x);
        int iv = __popc(bl);
        h_s[n * HD + lane] =
            sc.y * fmaf(sc.x, __ldg(&g_A[iv * HD + lane]),
                              __ldg(&g_C[iv * HD + lane]));
    }
    __syncthreads();

    // ---- pass D: layer-2 aggregation (float4, 4 nodes/warp, x2 unroll) ----
    {
        const int li  = lane & 7;
        const int sub = lane >> 3;
        const float4 b24 = *(const float4*)&b2_s[li * 4];
        const float4 w34 = *(const float4*)&W3_s[li * 4];
        const float4* hb = (const float4*)h_s;
        #pragma unroll
        for (int ps = 0; ps < 4; ps++) {
            const int n = (warp << 4) + ps * 4 + sub;
            const float di = sc_s[n].y;
            float4 acc  = hb[n * 8 + li];            // self term (h')
            float4 acc2 = make_float4(0.f, 0.f, 0.f, 0.f);
            const int beg = ptr_s[n], end = ptr_s[n + 1];
            int s = beg;
            for (; s + 1 < end; s += 2) {
                float2 f0 = ns_s[s];
                float2 f1 = ns_s[s + 1];
                float4 h0 = hb[__float_as_int(f0.y) + li];
                float4 h1 = hb[__float_as_int(f1.y) + li];
                acc.x  = fmaf(f0.x, h0.x, acc.x);
                acc.y  = fmaf(f0.x, h0.y, acc.y);
                acc.z  = fmaf(f0.x, h0.z, acc.z);
                acc.w  = fmaf(f0.x, h0.w, acc.w);
                acc2.x = fmaf(f1.x, h1.x, acc2.x);
                acc2.y = fmaf(f1.x, h1.y, acc2.y);
                acc2.z = fmaf(f1.x, h1.z, acc2.z);
                acc2.w = fmaf(f1.x, h1.w, acc2.w);
            }
            if (s < end) {
                float2 f0 = ns_s[s];
                float4 h0 = hb[__float_as_int(f0.y) + li];
                acc.x = fmaf(f0.x, h0.x, acc.x);
                acc.y = fmaf(f0.x, h0.y, acc.y);
                acc.z = fmaf(f0.x, h0.z, acc.z);
                acc.w = fmaf(f0.x, h0.w, acc.w);
            }
            acc.x += acc2.x; acc.y += acc2.y; acc.z += acc2.z; acc.w += acc2.w;
            float v = fmaxf(fmaf(di, acc.x, b24.x), 0.f) * w34.x
                    + fmaxf(fmaf(di, acc.y, b24.y), 0.f) * w34.y
                    + fmaxf(fmaf(di, acc.z, b24.z), 0.f) * w34.z
                    + fmaxf(fmaf(di, acc.w, b24.w), 0.f) * w34.w;
            v += __shfl_xor_sync(0xffffffffu, v, 4);
            v += __shfl_xor_sync(0xffffffffu, v, 2);
            v += __shfl_xor_sync(0xffffffffu, v, 1);
            if (li == 0) h3_s[n] = di * v;           // pre-scaled t'
        }
    }
    __syncthreads();

    // ---- pass E: layer-3 scalar aggregation (x2 unroll) -> output ----
    if (tid < NUMK) {
        float acc = h3_s[tid], acc2 = 0.f;
        int s = begN;
        for (; s + 1 < endN; s += 2) {
            float2 f0 = ns_s[s];
            float2 f1 = ns_s[s + 1];
            acc  = fmaf(f0.x, h3_s[__float_as_int(f0.y) >> 3], acc);
            acc2 = fmaf(f1.x, h3_s[__float_as_int(f1.y) >> 3], acc2);
        }
        if (s < endN) {
            float2 f0 = ns_s[s];
            acc = fmaf(f0.x, h3_s[__float_as_int(f0.y) >> 3], acc);
        }
        out[(long long)g * NUMK + tid] =
            fmaf(deg_s[tid], acc + acc2, __ldg(&b3[0]));
    }
}

extern "C" void kernel_launch(void* const* d_in, const int* in_sizes, int n_in,
                              void* d_out, int out_size) {
    const float* Hx = (const float*)d_in[0];
    const int*   ei = (const int*)d_in[1];
    const float* W1 = (const float*)d_in[2];
    const float* b1 = (const float*)d_in[3];
    const float* W2 = (const float*)d_in[4];
    const float* b2 = (const float*)d_in[5];
    const float* W3 = (const float*)d_in[6];
    const float* b3 = (const float*)d_in[7];
    float* out = (float*)d_out;

    gcn_prep<<<34, 256>>>(ei, W1, b1, W2);
    gcn_main<<<NGRAPHS, 256>>>(Hx, b2, W3, b3, out);
}

// round 7
// speedup vs baseline: 1.6177x; 1.1862x over previous
#include <cuda_runtime.h>
#include <math_constants.h>

#define NGRAPHS 2048
#define NUMK    128
#define NE      1024
#define HD      32
#define ROWLEN  (NUMK + NE + 2)

// Built once per launch (edge template + weights identical across graphs).
// All node ids below are DEGREE-SORTED RANKS, not original node ids.
__device__ int g_csr[NE];                       // packed: src_rank | dst_rank<<8 | eid<<16
__device__ int g_ptr[NUMK + 1];                 // CSR ptr over dst ranks
__device__ int g_rank[NUMK];                    // original node -> rank
__device__ float g_t[HD];                       // relu thresholds t_k = -b1k/W1k
__device__ __align__(16) float g_A[33 * HD];    // h = s1*A[iv] + C[iv]
__device__ __align__(16) float g_C[33 * HD];

// ---- single prep launch: block 0 = rank+CSR build; blocks 1..33 = tables ----
__global__ __launch_bounds__(256) void gcn_prep(const int* __restrict__ ew,
                                                const float* __restrict__ W1,
                                                const float* __restrict__ b1,
                                                const float* __restrict__ W2) {
    if (blockIdx.x == 0) {
        __shared__ unsigned char src_sh[NE], dst_sh[NE];
        __shared__ int cnt[NUMK];                // node-space counts, reused as fill cursor
        __shared__ int rank_sh[NUMK];
        __shared__ int cntr[NUMK];               // rank-space counts
        __shared__ int base_sh[NUMK + 1];
        __shared__ int wsum[4];
        __shared__ int odd_nonzero;
        const int t = threadIdx.x;
        if (t == 0) odd_nonzero = 0;
        if (t < NUMK) cnt[t] = 0;
        __syncthreads();
        // int32 vs int64 layout guard: odd words all-zero => little-endian int64
        int nz = 0;
        for (int i = t * 2 + 1; i < 2 * NE; i += 512) nz |= ew[i];
        if (nz) odd_nonzero = 1;
        __syncthreads();
        const bool is64 = (odd_nonzero == 0);
        for (int e = t; e < NE; e += 256) {
            int s, d;
            if (is64) { s = ew[2 * e]; d = ew[2 * (NE + e)]; }
            else      { s = ew[e];     d = ew[NE + e]; }
            src_sh[e] = (unsigned char)(s & 127);
            dst_sh[e] = (unsigned char)(d & 127);
        }
        __syncthreads();
        for (int e = t; e < NE; e += 256) atomicAdd(&cnt[dst_sh[e]], 1);
        __syncthreads();
        // degree rank (ascending, stable) — O(128) per thread
        if (t < NUMK) {
            int c = cnt[t], r = 0;
            for (int m = 0; m < NUMK; m++) {
                int cm = cnt[m];
                r += (cm < c) || (cm == c && m < t);
            }
            rank_sh[t] = r;
            g_rank[t]  = r;
            cntr[r]    = c;
        }
        __syncthreads();
        // exclusive prefix over rank-space counts (warp scans + offsets)
        if (t < NUMK) {
            int lane = t & 31, w = t >> 5;
            int v = cntr[t];
            int sc = v;
            #pragma unroll
            for (int o = 1; o < 32; o <<= 1) {
                int u = __shfl_up_sync(0xffffffffu, sc, o);
                if (lane >= o) sc += u;
            }
            if (lane == 31) wsum[w] = sc;
            __syncwarp();
        }
        __syncthreads();
        if (t < NUMK) {
            int lane = t & 31, w = t >> 5;
            int off = 0;
            for (int i = 0; i < w; i++) off += wsum[i];
            int v = cntr[t];
            int sc = v;
            #pragma unroll
            for (int o = 1; o < 32; o <<= 1) {
                int u = __shfl_up_sync(0xffffffffu, sc, o);
                if (lane >= o) sc += u;
            }
            base_sh[t] = off + sc - v;
            if (t == 127) base_sh[NUMK] = off + sc;
            g_ptr[t] = off + sc - v;
            if (t == 127) g_ptr[NUMK] = off + sc;
            cnt[t] = 0;                          // reuse as fill cursor (rank space)
        }
        __syncthreads();
        for (int e = t; e < NE; e += 256) {
            int dr = rank_sh[dst_sh[e]];
            int sr = rank_sh[src_sh[e]];
            int pos = base_sh[dr] + atomicAdd(&cnt[dr], 1);
            if (pos < NE)
                g_csr[pos] = sr | (dr << 8) | (e << 16);
        }
    } else {
        // ---------- piecewise-linear table row (warp 0 only) ----------
        const int j = threadIdx.x;
        if (j >= 32) return;
        __shared__ float t_sh[HD], w1_sh[HD], b1_sh[HD], tsort[HD];
        __shared__ unsigned int mask_sh;
        const int iv = blockIdx.x - 1;           // 0..32
        float w1 = W1[j], bv = b1[j];
        w1_sh[j] = w1; b1_sh[j] = bv;
        float tk = (w1 == 0.f) ? CUDART_INF_F : (-bv / w1);
        t_sh[j] = tk;
        if (iv == 0) g_t[j] = tk;
        __syncwarp();
        int r = 0;
        #pragma unroll
        for (int m = 0; m < HD; m++) {
            float tm = t_sh[m];
            r += (tm < tk) || (tm == tk && m < j);
        }
        tsort[r] = tk;
        __syncwarp();
        if (j == 0) {
            float s;
            if (iv == 0)       s = tsort[0] - fabsf(tsort[0]) - 1.f;
            else if (iv == 32) s = tsort[31] + fabsf(tsort[31]) + 1.f;
            else               s = 0.5f * (tsort[iv - 1] + tsort[iv]);
            unsigned m = 0;
            for (int k = 0; k < HD; k++) {
                float w = w1_sh[k], tt = t_sh[k];
                bool act = (w > 0.f) ? (s > tt)
                         : (w < 0.f) ? (s < tt)
                                     : (b1_sh[k] > 0.f);
                if (act) m |= 1u << k;
            }
            mask_sh = m;
        }
        __syncwarp();
        const unsigned m = mask_sh;
        float accA = 0.f, accC = 0.f;
        #pragma unroll
        for (int k = 0; k < HD; k++) {
            if ((m >> k) & 1u) {
                float w2 = __ldg(&W2[k * HD + j]);
                accA = fmaf(w1_sh[k], w2, accA);
                accC = fmaf(b1_sh[k], w2, accC);
            }
        }
        g_A[iv * HD + j] = accA;
        g_C[iv * HD + j] = accC;
    }
}

// One CTA per graph, 256 threads, everything in degree-rank space.
// norm never materialized: vectors pre-scaled by dinv, post-scaled by dinv_dst.
__global__ __launch_bounds__(256, 6) void gcn_main(
    const float* __restrict__ Hx,
    const float* __restrict__ b2,
    const float* __restrict__ W3,
    const float* __restrict__ b3,
    float* __restrict__ out)
{
    __shared__ float  p_s[NUMK];                 // p (rank space), then p' = dinv*p
    __shared__ float  w_s[NE];
    __shared__ int    ptr_s[NUMK + 1];
    __shared__ int    rank_s[NUMK];
    __shared__ float  dinv_s[NUMK];
    __shared__ float2 sc_s[NUMK];                // (s1_final, dinv)
    __shared__ float  h3_s[NUMK];                // t' (pre-scaled layer-2 out scalar)
    __shared__ float  res_s[NUMK];               // final per-rank result
    __shared__ float2 ns_s[NE];                  // (w, src_rank*8)
    __shared__ __align__(16) float h_s[NUMK * HD];
    __shared__ __align__(16) float b2_s[HD], W3_s[HD];

    const int g    = blockIdx.x;
    const int tid  = threadIdx.x;
    const int lane = tid & 31;
    const int warp = tid >> 5;
    const int node = tid >> 1;                   // rank, 2 threads per node
    const int par  = tid & 1;
    const float* row = Hx + (long long)g * ROWLEN;

    // ---- stage ----
    {
        if (tid < NUMK) {
            int rk = __ldg(&g_rank[tid]);
            rank_s[tid] = rk;
            p_s[rk] = row[tid];                  // permute p into rank space
        }
        const float2* rp = (const float2*)row;
        for (int i = tid; i < NE / 2; i += 256) {
            float2 v = rp[64 + i];
            w_s[2 * i] = v.x; w_s[2 * i + 1] = v.y;
        }
        if (tid <= NUMK) ptr_s[tid] = g_ptr[tid];
        if (tid < HD) { b2_s[tid] = b2[tid]; W3_s[tid] = W3[tid]; }
    }
    const float tl = __ldg(&g_t[lane]);
    __syncthreads();

    // ---- pass A: 2 threads/node — stash (w, src*8), reduce degree, scale p ----
    const int begN = ptr_s[node], endN = ptr_s[node + 1];
    {
        float deg = 0.f;
        for (int s = begN + par; s < endN; s += 2) {
            int pk = __ldg(&g_csr[s]);
            float w = w_s[(pk >> 16) & 1023];
            ns_s[s] = make_float2(w, __int_as_float((pk & 255) * 8));
            deg += w;
        }
        deg += __shfl_xor_sync(0xffffffffu, deg, 1);
        deg += 1.0f;                             // self-loop
        if (par == 0) {
            float di = rsqrtf(deg);              // deg >= 1 always
            dinv_s[node] = di;
            p_s[node]   *= di;                   // p'
        }
    }
    __syncthreads();

    // ---- pass B: 2 threads/node — layer-1 scalar aggregation ----
    {
        float acc = 0.f;
        for (int s = begN + par; s < endN; s += 2) {
            float2 f = ns_s[s];
            acc = fmaf(f.x, p_s[__float_as_int(f.y) >> 3], acc);
        }
        acc += __shfl_xor_sync(0xffffffffu, acc, 1);
        if (par == 0) {
            float di = dinv_s[node];
            sc_s[node] = make_float2(di * (acc + p_s[node]), di);
        }
    }
    __syncthreads();

    // ---- pass C: h' = dinv*(s1*A[iv] + C[iv]) via ballot interval lookup ----
    #pragma unroll
    for (int i = 0; i < 16; i++) {
        const int n = (warp << 4) + i;
        float2 sc = sc_s[n];
        unsigned bl = __ballot_sync(0xffffffffu, tl < sc.x);
        int iv = __popc(bl);
        h_s[n * HD + lane] =
            sc.y * fmaf(sc.x, __ldg(&g_A[iv * HD + lane]),
                              __ldg(&g_C[iv * HD + lane]));
    }
    __syncthreads();

    // ---- pass D: layer-2 aggregation, 4 nodes/warp, degree-balanced groups ----
    {
        const int li  = lane & 7;
        const int sub = lane >> 3;
        const float4 b24 = *(const float4*)&b2_s[li * 4];
        const float4 w34 = *(const float4*)&W3_s[li * 4];
        const float4* hb = (const float4*)h_s;
        #pragma unroll
        for (int ps = 0; ps < 4; ps++) {
            const int q = ps * 8 + warp;         // stripe groups across warps
            const int n = q * 4 + sub;           // 4 consecutive ranks per group
            const float di = sc_s[n].y;
            float4 acc  = hb[n * 8 + li];        // self term (h')
            float4 acc2 = make_float4(0.f, 0.f, 0.f, 0.f);
            const int beg = ptr_s[n], end = ptr_s[n + 1];
            int s = beg;
            for (; s + 1 < end; s += 2) {
                float2 f0 = ns_s[s];
                float2 f1 = ns_s[s + 1];
                float4 h0 = hb[__float_as_int(f0.y) + li];
                float4 h1 = hb[__float_as_int(f1.y) + li];
                acc.x  = fmaf(f0.x, h0.x, acc.x);
                acc.y  = fmaf(f0.x, h0.y, acc.y);
                acc.z  = fmaf(f0.x, h0.z, acc.z);
                acc.w  = fmaf(f0.x, h0.w, acc.w);
                acc2.x = fmaf(f1.x, h1.x, acc2.x);
                acc2.y = fmaf(f1.x, h1.y, acc2.y);
                acc2.z = fmaf(f1.x, h1.z, acc2.z);
                acc2.w = fmaf(f1.x, h1.w, acc2.w);
            }
            if (s < end) {
                float2 f0 = ns_s[s];
                float4 h0 = hb[__float_as_int(f0.y) + li];
                acc.x = fmaf(f0.x, h0.x, acc.x);
                acc.y = fmaf(f0.x, h0.y, acc.y);
                acc.z = fmaf(f0.x, h0.z, acc.z);
                acc.w = fmaf(f0.x, h0.w, acc.w);
            }
            acc.x += acc2.x; acc.y += acc2.y; acc.z += acc2.z; acc.w += acc2.w;
            float v = fmaxf(fmaf(di, acc.x, b24.x), 0.f) * w34.x
                    + fmaxf(fmaf(di, acc.y, b24.y), 0.f) * w34.y
                    + fmaxf(fmaf(di, acc.z, b24.z), 0.f) * w34.z
                    + fmaxf(fmaf(di, acc.w, b24.w), 0.f) * w34.w;
            v += __shfl_xor_sync(0xffffffffu, v, 4);
            v += __shfl_xor_sync(0xffffffffu, v, 2);
            v += __shfl_xor_sync(0xffffffffu, v, 1);
            if (li == 0) h3_s[n] = di * v;       // pre-scaled t'
        }
    }
    __syncthreads();

    // ---- pass E: 2 threads/node — layer-3 scalar aggregation ----
    {
        float acc = 0.f;
        for (int s = begN + par; s < endN; s += 2) {
            float2 f = ns_s[s];
            acc = fmaf(f.x, h3_s[__float_as_int(f.y) >> 3], acc);
        }
        acc += __shfl_xor_sync(0xffffffffu, acc, 1);
        if (par == 0)
            res_s[node] = fmaf(dinv_s[node], acc + h3_s[node], __ldg(&b3[0]));
    }
    __syncthreads();

    // ---- output: remap rank -> original node order, coalesced store ----
    if (tid < NUMK)
        out[(long long)g * NUMK + tid] = res_s[rank_s[tid]];
}

extern "C" void kernel_launch(void* const* d_in, const int* in_sizes, int n_in,
                              void* d_out, int out_size) {
    const float* Hx = (const float*)d_in[0];
    const int*   ei = (const int*)d_in[1];
    const float* W1 = (const float*)d_in[2];
    const float* b1 = (const float*)d_in[3];
    const float* W2 = (const float*)d_in[4];
    const float* b2 = (const float*)d_in[5];
    const float* W3 = (const float*)d_in[6];
    const float* b3 = (const float*)d_in[7];
    float* out = (float*)d_out;

    gcn_prep<<<34, 256>>>(ei, W1, b1, W2);
    gcn_main<<<NGRAPHS, 256>>>(Hx, b2, W3, b3, out);
}

// round 8
// speedup vs baseline: 1.9709x; 1.2183x over previous
#include <cuda_runtime.h>
#include <cuda_fp16.h>
#include <math_constants.h>

#define NGRAPHS 2048
#define NUMK    128
#define NE      1024
#define HD      32
#define ROWLEN  (NUMK + NE + 2)

// Built once per launch (edge template + weights identical across graphs).
// All node ids below are DEGREE-SORTED RANKS, not original node ids.
__device__ int g_csr[NE];                       // packed: src_rank | dst_rank<<8 | eid<<16
__device__ int g_ptr[NUMK + 1];                 // CSR ptr over dst ranks
__device__ int g_rank[NUMK];                    // original node -> rank
__device__ float g_t[HD];                       // relu thresholds t_k = -b1k/W1k
__device__ __align__(16) float g_A[33 * HD];    // h = s1*A[iv] + C[iv]
__device__ __align__(16) float g_C[33 * HD];

// ---- single prep launch: block 0 = rank+CSR build; blocks 1..33 = tables ----
__global__ __launch_bounds__(256) void gcn_prep(const int* __restrict__ ew,
                                                const float* __restrict__ W1,
                                                const float* __restrict__ b1,
                                                const float* __restrict__ W2) {
    if (blockIdx.x == 0) {
        __shared__ unsigned char src_sh[NE], dst_sh[NE];
        __shared__ int cnt[NUMK];
        __shared__ int rank_sh[NUMK];
        __shared__ int cntr[NUMK];
        __shared__ int base_sh[NUMK + 1];
        __shared__ int wsum[4];
        __shared__ int odd_nonzero;
        const int t = threadIdx.x;
        if (t == 0) odd_nonzero = 0;
        if (t < NUMK) cnt[t] = 0;
        __syncthreads();
        // int32 vs int64 layout guard: odd words all-zero => little-endian int64
        int nz = 0;
        for (int i = t * 2 + 1; i < 2 * NE; i += 512) nz |= ew[i];
        if (nz) odd_nonzero = 1;
        __syncthreads();
        const bool is64 = (odd_nonzero == 0);
        for (int e = t; e < NE; e += 256) {
            int s, d;
            if (is64) { s = ew[2 * e]; d = ew[2 * (NE + e)]; }
            else      { s = ew[e];     d = ew[NE + e]; }
            src_sh[e] = (unsigned char)(s & 127);
            dst_sh[e] = (unsigned char)(d & 127);
        }
        __syncthreads();
        for (int e = t; e < NE; e += 256) atomicAdd(&cnt[dst_sh[e]], 1);
        __syncthreads();
        // degree rank (ascending, stable)
        if (t < NUMK) {
            int c = cnt[t], r = 0;
            for (int m = 0; m < NUMK; m++) {
                int cm = cnt[m];
                r += (cm < c) || (cm == c && m < t);
            }
            rank_sh[t] = r;
            g_rank[t]  = r;
            cntr[r]    = c;
        }
        __syncthreads();
        if (t < NUMK) {
            int lane = t & 31, w = t >> 5;
            int v = cntr[t];
            int sc = v;
            #pragma unroll
            for (int o = 1; o < 32; o <<= 1) {
                int u = __shfl_up_sync(0xffffffffu, sc, o);
                if (lane >= o) sc += u;
            }
            if (lane == 31) wsum[w] = sc;
            __syncwarp();
        }
        __syncthreads();
        if (t < NUMK) {
            int lane = t & 31, w = t >> 5;
            int off = 0;
            for (int i = 0; i < w; i++) off += wsum[i];
            int v = cntr[t];
            int sc = v;
            #pragma unroll
            for (int o = 1; o < 32; o <<= 1) {
                int u = __shfl_up_sync(0xffffffffu, sc, o);
                if (lane >= o) sc += u;
            }
            base_sh[t] = off + sc - v;
            if (t == 127) base_sh[NUMK] = off + sc;
            g_ptr[t] = off + sc - v;
            if (t == 127) g_ptr[NUMK] = off + sc;
            cnt[t] = 0;
        }
        __syncthreads();
        for (int e = t; e < NE; e += 256) {
            int dr = rank_sh[dst_sh[e]];
            int sr = rank_sh[src_sh[e]];
            int pos = base_sh[dr] + atomicAdd(&cnt[dr], 1);
            if (pos < NE)
                g_csr[pos] = sr | (dr << 8) | (e << 16);
        }
    } else {
        // ---------- piecewise-linear table row (warp 0 only) ----------
        const int j = threadIdx.x;
        if (j >= 32) return;
        __shared__ float t_sh[HD], w1_sh[HD], b1_sh[HD], tsort[HD];
        __shared__ unsigned int mask_sh;
        const int iv = blockIdx.x - 1;           // 0..32
        float w1 = W1[j], bv = b1[j];
        w1_sh[j] = w1; b1_sh[j] = bv;
        float tk = (w1 == 0.f) ? CUDART_INF_F : (-bv / w1);
        t_sh[j] = tk;
        if (iv == 0) g_t[j] = tk;
        __syncwarp();
        int r = 0;
        #pragma unroll
        for (int m = 0; m < HD; m++) {
            float tm = t_sh[m];
            r += (tm < tk) || (tm == tk && m < j);
        }
        tsort[r] = tk;
        __syncwarp();
        if (j == 0) {
            float s;
            if (iv == 0)       s = tsort[0] - fabsf(tsort[0]) - 1.f;
            else if (iv == 32) s = tsort[31] + fabsf(tsort[31]) + 1.f;
            else               s = 0.5f * (tsort[iv - 1] + tsort[iv]);
            unsigned m = 0;
            for (int k = 0; k < HD; k++) {
                float w = w1_sh[k], tt = t_sh[k];
                bool act = (w > 0.f) ? (s > tt)
                         : (w < 0.f) ? (s < tt)
                                     : (b1_sh[k] > 0.f);
                if (act) m |= 1u << k;
            }
            mask_sh = m;
        }
        __syncwarp();
        const unsigned m = mask_sh;
        float accA = 0.f, accC = 0.f;
        #pragma unroll
        for (int k = 0; k < HD; k++) {
            if ((m >> k) & 1u) {
                float w2 = __ldg(&W2[k * HD + j]);
                accA = fmaf(w1_sh[k], w2, accA);
                accC = fmaf(b1_sh[k], w2, accC);
            }
        }
        g_A[iv * HD + j] = accA;
        g_C[iv * HD + j] = accC;
    }
}

// One CTA per graph, 256 threads, everything in degree-rank space.
// norm never materialized: vectors pre-scaled by dinv, post-scaled by dinv_dst.
// h stored fp16 (fp32 accumulate); ns packed: half(w)<<16 | src_rank*16.
__global__ __launch_bounds__(256, 6) void gcn_main(
    const float* __restrict__ Hx,
    const float* __restrict__ b2,
    const float* __restrict__ W3,
    const float* __restrict__ b3,
    float* __restrict__ out)
{
    __shared__ float  p_s[NUMK];                 // p (rank space), then p' = dinv*p
    __shared__ float  w_s[NE];
    __shared__ int    ptr_s[NUMK + 1];
    __shared__ int    rank_s[NUMK];
    __shared__ float  dinv_s[NUMK];
    __shared__ float2 sc_s[NUMK];                // (s1_final, dinv)
    __shared__ float  h3_s[NUMK];                // t' (pre-scaled layer-2 out scalar)
    __shared__ float  res_s[NUMK];               // final per-rank result
    __shared__ unsigned int ns_s[NE];            // half(w)<<16 | src_rank*16
    __shared__ __align__(16) unsigned int h2_s[NUMK * 16];  // fp16 h, 16 u32/row
    __shared__ __align__(16) float b2_s[HD], W3_s[HD];

    const int g    = blockIdx.x;
    const int tid  = threadIdx.x;
    const int lane = tid & 31;
    const int warp = tid >> 5;
    const int node = tid >> 1;                   // rank, 2 threads per node
    const int par  = tid & 1;
    const float* row = Hx + (long long)g * ROWLEN;

    // ---- stage ----
    {
        if (tid < NUMK) {
            int rk = __ldg(&g_rank[tid]);
            rank_s[tid] = rk;
            p_s[rk] = row[tid];                  // permute p into rank space
        }
        const float2* rp = (const float2*)row;
        for (int i = tid; i < NE / 2; i += 256) {
            float2 v = rp[64 + i];
            w_s[2 * i] = v.x; w_s[2 * i + 1] = v.y;
        }
        if (tid <= NUMK) ptr_s[tid] = g_ptr[tid];
        if (tid < HD) { b2_s[tid] = b2[tid]; W3_s[tid] = W3[tid]; }
    }
    const float tl = __ldg(&g_t[lane]);
    __syncthreads();

    // ---- pass A: 2 threads/node — pack ns, reduce degree, scale p ----
    const int begN = ptr_s[node], endN = ptr_s[node + 1];
    {
        float deg = 0.f;
        for (int s = begN + par; s < endN; s += 2) {
            int pk = __ldg(&g_csr[s]);
            float w = w_s[(pk >> 16) & 1023];
            unsigned hw = (unsigned)__half_as_ushort(__float2half_rn(w));
            ns_s[s] = (hw << 16) | (unsigned)((pk & 255) * 16);
            deg += w;
        }
        deg += __shfl_xor_sync(0xffffffffu, deg, 1);
        deg += 1.0f;                             // self-loop
        if (par == 0) {
            float di = rsqrtf(deg);              // deg >= 1 always
            dinv_s[node] = di;
            p_s[node]   *= di;                   // p'
        }
    }
    __syncthreads();

    // ---- pass B: 2 threads/node — layer-1 scalar aggregation ----
    {
        float acc = 0.f;
        for (int s = begN + par; s < endN; s += 2) {
            unsigned k = ns_s[s];
            float w = __half2float(__ushort_as_half((unsigned short)(k >> 16)));
            acc = fmaf(w, p_s[(k & 0xffffu) >> 4], acc);
        }
        acc += __shfl_xor_sync(0xffffffffu, acc, 1);
        if (par == 0) {
            float di = dinv_s[node];
            sc_s[node] = make_float2(di * (acc + p_s[node]), di);
        }
    }
    __syncthreads();

    // ---- pass C: h' = dinv*(s1*A[iv] + C[iv]); store fp16 ----
    {
        __half* hh = (__half*)h2_s;
        #pragma unroll
        for (int i = 0; i < 16; i++) {
            const int n = (warp << 4) + i;
            float2 sc = sc_s[n];
            unsigned bl = __ballot_sync(0xffffffffu, tl < sc.x);
            int iv = __popc(bl);
            float v = sc.y * fmaf(sc.x, __ldg(&g_A[iv * HD + lane]),
                                        __ldg(&g_C[iv * HD + lane]));
            hh[n * HD + lane] = __float2half_rn(v);
        }
    }
    __syncthreads();

    // ---- pass D: layer-2 aggregation, 4 nodes/warp, degree-balanced groups ----
    {
        const int li  = lane & 7;
        const int sub = lane >> 3;
        const float4 b24 = *(const float4*)&b2_s[li * 4];
        const float4 w34 = *(const float4*)&W3_s[li * 4];
        #pragma unroll
        for (int ps = 0; ps < 4; ps++) {
            const int q = ps * 8 + warp;         // stripe groups across warps
            const int n = q * 4 + sub;           // 4 consecutive ranks per group
            const float di = sc_s[n].y;
            // self term (h' row, fp16 -> fp32)
            uint2 su = *(const uint2*)&h2_s[n * 16 + 2 * li];
            float2 s0 = __half22float2(*(const __half2*)&su.x);
            float2 s1 = __half22float2(*(const __half2*)&su.y);
            float4 acc  = make_float4(s0.x, s0.y, s1.x, s1.y);
            float4 acc2 = make_float4(0.f, 0.f, 0.f, 0.f);
            const int beg = ptr_s[n], end = ptr_s[n + 1];
            int s = beg;
            for (; s + 1 < end; s += 2) {
                unsigned k0 = ns_s[s], k1 = ns_s[s + 1];
                float w0 = __half2float(__ushort_as_half((unsigned short)(k0 >> 16)));
                float w1 = __half2float(__ushort_as_half((unsigned short)(k1 >> 16)));
                uint2 u0 = *(const uint2*)&h2_s[(k0 & 0xffffu) + 2 * li];
                uint2 u1 = *(const uint2*)&h2_s[(k1 & 0xffffu) + 2 * li];
                float2 a0 = __half22float2(*(const __half2*)&u0.x);
                float2 a1 = __half22float2(*(const __half2*)&u0.y);
                float2 c0 = __half22float2(*(const __half2*)&u1.x);
                float2 c1 = __half22float2(*(const __half2*)&u1.y);
                acc.x  = fmaf(w0, a0.x, acc.x);
                acc.y  = fmaf(w0, a0.y, acc.y);
                acc.z  = fmaf(w0, a1.x, acc.z);
                acc.w  = fmaf(w0, a1.y, acc.w);
                acc2.x = fmaf(w1, c0.x, acc2.x);
                acc2.y = fmaf(w1, c0.y, acc2.y);
                acc2.z = fmaf(w1, c1.x, acc2.z);
                acc2.w = fmaf(w1, c1.y, acc2.w);
            }
            if (s < end) {
                unsigned k0 = ns_s[s];
                float w0 = __half2float(__ushort_as_half((unsigned short)(k0 >> 16)));
                uint2 u0 = *(const uint2*)&h2_s[(k0 & 0xffffu) + 2 * li];
                float2 a0 = __half22float2(*(const __half2*)&u0.x);
                float2 a1 = __half22float2(*(const __half2*)&u0.y);
                acc.x = fmaf(w0, a0.x, acc.x);
                acc.y = fmaf(w0, a0.y, acc.y);
                acc.z = fmaf(w0, a1.x, acc.z);
                acc.w = fmaf(w0, a1.y, acc.w);
            }
            acc.x += acc2.x; acc.y += acc2.y; acc.z += acc2.z; acc.w += acc2.w;
            float v = fmaxf(fmaf(di, acc.x, b24.x), 0.f) * w34.x
                    + fmaxf(fmaf(di, acc.y, b24.y), 0.f) * w34.y
                    + fmaxf(fmaf(di, acc.z, b24.z), 0.f) * w34.z
                    + fmaxf(fmaf(di, acc.w, b24.w), 0.f) * w34.w;
            v += __shfl_xor_sync(0xffffffffu, v, 4);
            v += __shfl_xor_sync(0xffffffffu, v, 2);
            v += __shfl_xor_sync(0xffffffffu, v, 1);
            if (li == 0) h3_s[n] = di * v;       // pre-scaled t'
        }
    }
    __syncthreads();

    // ---- pass E: 2 threads/node — layer-3 scalar aggregation ----
    {
        float acc = 0.f;
        for (int s = begN + par; s < endN; s += 2) {
            unsigned k = ns_s[s];
            float w = __half2float(__ushort_as_half((unsigned short)(k >> 16)));
            acc = fmaf(w, h3_s[(k & 0xffffu) >> 4], acc);
        }
        acc += __shfl_xor_sync(0xffffffffu, acc, 1);
        if (par == 0)
            res_s[node] = fmaf(dinv_s[node], acc + h3_s[node], __ldg(&b3[0]));
    }
    __syncthreads();

    // ---- output: remap rank -> original node order, coalesced store ----
    if (tid < NUMK)
        out[(long long)g * NUMK + tid] = res_s[rank_s[tid]];
}

extern "C" void kernel_launch(void* const* d_in, const int* in_sizes, int n_in,
                              void* d_out, int out_size) {
    const float* Hx = (const float*)d_in[0];
    const int*   ei = (const int*)d_in[1];
    const float* W1 = (const float*)d_in[2];
    const float* b1 = (const float*)d_in[3];
    const float* W2 = (const float*)d_in[4];
    const float* b2 = (const float*)d_in[5];
    const float* W3 = (const float*)d_in[6];
    const float* b3 = (const float*)d_in[7];
    float* out = (float*)d_out;

    gcn_prep<<<34, 256>>>(ei, W1, b1, W2);
    gcn_main<<<NGRAPHS, 256>>>(Hx, b2, W3, b3, out);
}